// round 15
// baseline (speedup 1.0000x reference)
#include <cuda_runtime.h>
#include <math.h>
#include <stdint.h>

typedef unsigned long long ull;

#define B_   64
#define L_   49
#define ENC_ 2048
#define TMX  59
#define V_   10000
#define BK   16
#define BM   64
#define BN   128
#define NBLK 296
#define HUGE_ 0x3FFFFFFF

#define ASTRIDE 68
#define SM_A_BYTES (2 * 16 * ASTRIDE * 4)          // 8704
#define SM_TOTAL   (SM_A_BYTES + 2 * 16 * 128 * 4) // 25088

#define HP_SLABS 320
#define GS_SLABS 512

// ---------------- scratch ----------------
__device__ float g_mean[B_ * ENC_];
__device__ float g_hc[B_ * 1024];
__device__ float g_hcslab[16 * B_ * 1024];
__device__ float g_encslab[2 * 3136 * 512];
__device__ float g_encproj[3136 * 512];
__device__ float g_emb[TMX * B_ * 512];
__device__ float g_hp[16 * B_ * 2560];
__device__ float g_gattv[B_ * 2048];
__device__ float g_gs[32 * B_ * 2048];
__device__ float g_hall[B_ * TMX * 512];     // row (b*59+t) x 512
__device__ int   g_rowmap[B_ * TMX];
__device__ int   g_nactive;
__device__ int   g_tk[TMX * 4];
__device__ unsigned int g_bar_count;
__device__ unsigned int g_bar_gen;

// ---------------- f32x2 helpers ----------------
__device__ __forceinline__ ull pk2(float lo, float hi) {
    ull r; asm("mov.b64 %0, {%1,%2};" : "=l"(r) : "f"(lo), "f"(hi)); return r;
}
__device__ __forceinline__ void fma2(ull& d, ull a, ull b) {
    asm("fma.rn.f32x2 %0, %1, %2, %0;" : "+l"(d) : "l"(a), "l"(b));
}
__device__ __forceinline__ float2 upk2(ull v) {
    float2 f; asm("mov.b64 {%0,%1}, %2;" : "=f"(f.x), "=f"(f.y) : "l"(v)); return f;
}

// =====================================================================
// GEMM body (R8 state): 256 threads, BM=64, BN=128, BK=16, f32x2,
// 2-chunk-ahead global register pipeline over double-buffered smem.
// =====================================================================
template<int KA0, int LDA0, int KA1, int LDA1, int LDA2,
         int WSPLITK, int WSPLITN, int LDWA, int LDWB,
         int NTOT, int KSLAB, int GATHER, int EPI>
__device__ __forceinline__ void gemm_body(
    const float* __restrict__ A0, const float* __restrict__ A1,
    const float* __restrict__ A2, const int* __restrict__ rowIdx,
    const float* __restrict__ Wa, const float* __restrict__ Wb,
    int Mtot,
    float* __restrict__ Cslab, long long slabStride,
    const float* __restrict__ bias, float* __restrict__ outPred,
    int bx, int by, int z, char* smemRaw)
{
    float* As = (float*)smemRaw;                    // [2][16][ASTRIDE]
    float* Ws = (float*)(smemRaw + SM_A_BYTES);     // [2][16][128]

    const int tid  = threadIdx.x;
    const int w    = tid >> 5, lane = tid & 31;
    const int lr   = lane >> 2, lc = lane & 3;
    const int row0 = by * BM;
    const int kbase = z * KSLAB;
    const int mlim = (EPI == 2) ? g_nactive : Mtot;

    if (EPI == 2) {
        if (row0 >= mlim) return;
    }

    float4 avf0, avf1;
    float4 wvf0[2], wvf1[2];

    auto loadAv = [&](int kb) -> float4 {
        int m  = tid >> 2;
        int k4 = (tid & 3) * 4;
        int k  = kb + k4;
        int mg = row0 + m;
        float4 v = make_float4(0.f, 0.f, 0.f, 0.f);
        if (mg < mlim) {
            int arow = rowIdx ? rowIdx[mg] : mg;
            const float* Ap; int kr, lda;
            if (k < KA0)            { Ap = A0; kr = k;             lda = LDA0; }
            else if (k < KA0 + KA1) { Ap = A1; kr = k - KA0;       lda = LDA1; }
            else                    { Ap = A2; kr = k - KA0 - KA1; lda = LDA2; }
            v = __ldcg((const float4*)&Ap[(size_t)arow * lda + kr]);
        }
        return v;
    };
    auto loadWv = [&](int kb, float4* wv) {
#pragma unroll
        for (int p = 0; p < 2; p++) {
            int id = tid + p * 256;
            int k  = kb + (id >> 5);
            int j4 = (id & 31) * 4;
            int pc = GATHER ? ((j4 >> 5) * 512 + bx * 32 + (j4 & 31)) : (bx * BN + j4);
            const float* Wp = Wa; int kr = k, cc = pc, ldw = LDWA;
            if (k >= WSPLITK)       { Wp = Wb; kr = k - WSPLITK;  ldw = LDWB; }
            else if (pc >= WSPLITN) { Wp = Wb; cc = pc - WSPLITN; ldw = LDWB; }
            float4 v;
            if (pc + 3 < NTOT) {
                v = *(const float4*)&Wp[(size_t)kr * ldw + cc];
            } else {
                v.x = (pc     < NTOT) ? Wp[(size_t)kr * ldw + cc]     : 0.f;
                v.y = (pc + 1 < NTOT) ? Wp[(size_t)kr * ldw + cc + 1] : 0.f;
                v.z = (pc + 2 < NTOT) ? Wp[(size_t)kr * ldw + cc + 2] : 0.f;
                v.w = 0.f;
            }
            wv[p] = v;
        }
    };

    ull acc[4][4];
#pragma unroll
    for (int r = 0; r < 4; r++)
#pragma unroll
        for (int c = 0; c < 4; c++) acc[r][c] = 0ull;

    constexpr int nCh = KSLAB / BK;
    static_assert(nCh % 2 == 0, "nCh must be even");

#define STAGE_FRAG(BUF, AV, WV)                                        \
    do {                                                               \
        int m_ = tid >> 2, k4_ = (tid & 3) * 4;                        \
        float* a_ = As + ((BUF) * 16 + k4_) * ASTRIDE + m_;            \
        a_[0]           = (AV).x;                                      \
        a_[ASTRIDE]     = (AV).y;                                      \
        a_[2 * ASTRIDE] = (AV).z;                                      \
        a_[3 * ASTRIDE] = (AV).w;                                      \
        {                                                              \
            int k_ = tid >> 5, j4_ = (tid & 31) * 4;                   \
            *(float4*)&Ws[((BUF) * 16 + k_) * 128 + j4_] = (WV)[0];    \
        }                                                              \
        {                                                              \
            int id_ = tid + 256;                                       \
            int k_ = id_ >> 5, j4_ = (id_ & 31) * 4;                   \
            *(float4*)&Ws[((BUF) * 16 + k_) * 128 + j4_] = (WV)[1];    \
        }                                                              \
    } while (0)

#define COMPUTE_CHUNK(BUF)                                             \
    do {                                                               \
        const float* Ab = As + (BUF) * (16 * ASTRIDE) + lr * 8;        \
        const float* Wp = Ws + (BUF) * (16 * 128) + w * 16 + lc * 4;   \
        _Pragma("unroll")                                              \
        for (int kk = 0; kk < BK; kk++) {                              \
            float4 a0 = *(const float4*)(Ab + kk * ASTRIDE);           \
            float4 a1 = *(const float4*)(Ab + kk * ASTRIDE + 4);       \
            float4 w4 = *(const float4*)(Wp + kk * 128);               \
            ull p0 = *(ull*)&a0.x, p1 = *(ull*)&a0.z;                  \
            ull p2 = *(ull*)&a1.x, p3 = *(ull*)&a1.z;                  \
            ull d0 = pk2(w4.x, w4.x), d1 = pk2(w4.y, w4.y);            \
            ull d2 = pk2(w4.z, w4.z), d3 = pk2(w4.w, w4.w);            \
            fma2(acc[0][0], p0, d0); fma2(acc[0][1], p0, d1);          \
            fma2(acc[0][2], p0, d2); fma2(acc[0][3], p0, d3);          \
            fma2(acc[1][0], p1, d0); fma2(acc[1][1], p1, d1);          \
            fma2(acc[1][2], p1, d2); fma2(acc[1][3], p1, d3);          \
            fma2(acc[2][0], p2, d0); fma2(acc[2][1], p2, d1);          \
            fma2(acc[2][2], p2, d2); fma2(acc[2][3], p2, d3);          \
            fma2(acc[3][0], p3, d0); fma2(acc[3][1], p3, d1);          \
            fma2(acc[3][2], p3, d2); fma2(acc[3][3], p3, d3);          \
        }                                                              \
    } while (0)

    avf0 = loadAv(kbase);            loadWv(kbase, wvf0);
    if (nCh > 1) { avf1 = loadAv(kbase + BK); loadWv(kbase + BK, wvf1); }
    STAGE_FRAG(0, avf0, wvf0);
    __syncthreads();

#pragma unroll 1
    for (int ch = 0; ch < nCh; ch += 2) {
        if (ch + 2 < nCh) { avf0 = loadAv(kbase + (ch + 2) * BK); loadWv(kbase + (ch + 2) * BK, wvf0); }
        COMPUTE_CHUNK(0);
        if (ch + 1 < nCh) STAGE_FRAG(1, avf1, wvf1);
        __syncthreads();

        if (ch + 3 < nCh) { avf1 = loadAv(kbase + (ch + 3) * BK); loadWv(kbase + (ch + 3) * BK, wvf1); }
        COMPUTE_CHUNK(1);
        if (ch + 2 < nCh) STAGE_FRAG(0, avf0, wvf0);
        __syncthreads();
    }
#undef STAGE_FRAG
#undef COMPUTE_CHUNK

    const int j0 = w * 16 + lc * 4;
#pragma unroll
    for (int rp = 0; rp < 4; rp++) {
#pragma unroll
        for (int half = 0; half < 2; half++) {
            int ml = row0 + lr * 8 + rp * 2 + half;
            if (ml >= mlim) continue;
            float v[4];
#pragma unroll
            for (int c = 0; c < 4; c++) {
                float2 f = upk2(acc[rp][c]);
                v[c] = half ? f.y : f.x;
            }
            if (EPI == 2) {
                int orow = rowIdx[ml];
                size_t base = (size_t)orow * V_;
                int pc0 = bx * BN + j0;
                if (pc0 + 3 < NTOT) {
                    float4 o;
                    o.x = v[0] + bias[pc0];     o.y = v[1] + bias[pc0 + 1];
                    o.z = v[2] + bias[pc0 + 2]; o.w = v[3] + bias[pc0 + 3];
                    *(float4*)&outPred[base + pc0] = o;
                } else {
#pragma unroll
                    for (int c = 0; c < 4; c++) {
                        int pc = pc0 + c;
                        if (pc < NTOT) outPred[base + pc] = v[c] + bias[pc];
                    }
                }
            } else {
                int pc0 = GATHER ? ((j0 >> 5) * 512 + bx * 32 + (j0 & 31)) : (bx * BN + j0);
                float* o = Cslab + (size_t)z * slabStride + (size_t)ml * NTOT + pc0;
                *(float4*)&o[0] = make_float4(v[0], v[1], v[2], v[3]);
            }
        }
    }
}

// ---------------- standalone GEMM wrappers ----------------
__global__ void __launch_bounds__(256, 2) gemm_h0c0(
    const float* h_w, const float* c_w)
{
    __shared__ char smem[SM_TOTAL];
    gemm_body<HUGE_, 2048, 0, 1, 1, HUGE_, 512, 512, 512, 1024, 128, 0, 0>(
        g_mean, g_mean, g_mean, nullptr, h_w, c_w, 64,
        g_hcslab, (long long)B_ * 1024, nullptr, nullptr,
        blockIdx.x, 0, blockIdx.z, smem);
}

__global__ void __launch_bounds__(256, 2) gemm_enc(
    const float* input, const float* enc_att_w)
{
    __shared__ char smem[SM_TOTAL];
    gemm_body<HUGE_, 2048, 0, 1, 1, HUGE_, HUGE_, 512, 512, 512, 1024, 0, 0>(
        input, input, input, nullptr, enc_att_w, enc_att_w, 3136,
        g_encslab, (long long)3136 * 512, nullptr, nullptr,
        blockIdx.x, blockIdx.y, blockIdx.z, smem);
}

__global__ void __launch_bounds__(256, 2) gemm_fc(
    const float* fc_w, const float* fc_b, float* out)
{
    __shared__ char smem[SM_TOTAL];
    gemm_body<HUGE_, 512, 0, 1, 1, HUGE_, HUGE_, V_, V_, V_, 512, 0, 2>(
        g_hall, g_hall, g_hall, g_rowmap, fc_w, fc_w, B_ * TMX,
        nullptr, 0, fc_b, out,
        blockIdx.x, blockIdx.y, 0, smem);
}

// ---------------- flat grid barrier (296 arrivals) ----------------
__device__ __forceinline__ void gbar() {
    __syncthreads();
    if (threadIdx.x == 0) {
        __threadfence();
        unsigned int gen = *(volatile unsigned int*)&g_bar_gen;
        unsigned int arrived = atomicAdd(&g_bar_count, 1u);
        if (arrived == NBLK - 1) {
            g_bar_count = 0;
            __threadfence();
            atomicAdd(&g_bar_gen, 1u);
        } else {
            while (*(volatile unsigned int*)&g_bar_gen == gen) {}
        }
        __threadfence();
    }
    __syncthreads();
}

// ---------------- attention phase (one block per b, 256 threads) ----------------
__device__ void attn_body(int b, int t,
    const float* __restrict__ input,
    const float* __restrict__ dec_b,
    const float* __restrict__ att_w,
    const float* __restrict__ att_b,
    const float* __restrict__ actv_b,
    const int* __restrict__ lens,
    float* __restrict__ outProbs, char* smemRaw)
{
    float* sd = (float*)smemRaw;   // 512
    float* sp = sd + 512;          // 64
    const int tid = threadIdx.x;

    for (int i = tid; i < 512; i += 256) {
        float s = dec_b[i];
#pragma unroll
        for (int zz = 0; zz < 16; zz++) s += __ldcg(&g_hp[zz * (B_ * 2560) + b * 2560 + i]);
        sd[i] = s;
    }
    __syncthreads();

    const int w = tid >> 5, lane = tid & 31;
    for (int l = w; l < L_; l += 8) {
        const float* ep = g_encproj + ((size_t)b * L_ + l) * 512;
        float s = 0.f;
#pragma unroll
        for (int a = lane; a < 512; a += 32) {
            float v = fmaxf(ep[a] + sd[a], 0.f);
            s = fmaf(v, att_w[a], s);
        }
#pragma unroll
        for (int o = 16; o; o >>= 1) s += __shfl_xor_sync(~0u, s, o);
        if (lane == 0) sp[l] = s + att_b[0];
    }
    __syncthreads();

    if (w == 0) {
        float v0 = (lane < L_) ? sp[lane] : -1e30f;
        float v1 = (lane + 32 < L_) ? sp[lane + 32] : -1e30f;
        float mx = fmaxf(v0, v1);
#pragma unroll
        for (int o = 16; o; o >>= 1) mx = fmaxf(mx, __shfl_xor_sync(~0u, mx, o));
        float e0 = (lane < L_) ? expf(v0 - mx) : 0.f;
        float e1 = (lane + 32 < L_) ? expf(v1 - mx) : 0.f;
        float sm = e0 + e1;
#pragma unroll
        for (int o = 16; o; o >>= 1) sm += __shfl_xor_sync(~0u, sm, o);
        float inv = 1.f / sm;
        if (lane < L_) sp[lane] = e0 * inv;
        if (lane + 32 < L_) sp[lane + 32] = e1 * inv;
    }
    __syncthreads();

    const bool act = t < (lens[b] - 1);
    if (tid < L_) outProbs[((size_t)b * TMX + t) * L_ + tid] = act ? sp[tid] : 0.f;

    const int e0i = tid * 8;
    float4 a0 = make_float4(0, 0, 0, 0), a1 = make_float4(0, 0, 0, 0);
    const float* ip = input + (size_t)b * L_ * ENC_ + e0i;
    for (int l = 0; l < L_; l++) {
        float p = sp[l];
        float4 x0 = *(const float4*)(ip + (size_t)l * ENC_);
        float4 x1 = *(const float4*)(ip + (size_t)l * ENC_ + 4);
        a0.x = fmaf(p, x0.x, a0.x); a0.y = fmaf(p, x0.y, a0.y);
        a0.z = fmaf(p, x0.z, a0.z); a0.w = fmaf(p, x0.w, a0.w);
        a1.x = fmaf(p, x1.x, a1.x); a1.y = fmaf(p, x1.y, a1.y);
        a1.z = fmaf(p, x1.z, a1.z); a1.w = fmaf(p, x1.w, a1.w);
    }
    float res[8] = {a0.x, a0.y, a0.z, a0.w, a1.x, a1.y, a1.z, a1.w};
#pragma unroll
    for (int i = 0; i < 8; i++) {
        int e = e0i + i;
        float hp = actv_b[e];
#pragma unroll
        for (int zz = 0; zz < 16; zz++) hp += __ldcg(&g_hp[zz * (B_ * 2560) + b * 2560 + 512 + e]);
        float gate = 1.f / (1.f + expf(-hp));
        g_gattv[b * ENC_ + e] = gate * res[i];
    }
}

// ---------------- lstm phase (128 slabs x 256 threads) ----------------
__device__ void lstm_body(int blk, int t,
    const float* __restrict__ bih, const float* __restrict__ bhh,
    const int* __restrict__ lens)
{
    int idx = blk * 256 + threadIdx.x;        // 64*512
    int b = idx >> 9, n = idx & 511;
    float gi = bih[n]        + bhh[n];
    float gf = bih[n + 512]  + bhh[n + 512];
    float gg = bih[n + 1024] + bhh[n + 1024];
    float go = bih[n + 1536] + bhh[n + 1536];
#pragma unroll
    for (int zz = 0; zz < 32; zz++) {
        const float* gs = g_gs + zz * (B_ * 2048) + b * 2048;
        gi += __ldcg(&gs[n]);        gf += __ldcg(&gs[n + 512]);
        gg += __ldcg(&gs[n + 1024]); go += __ldcg(&gs[n + 1536]);
    }
    float c  = __ldcg(&g_hc[b * 1024 + 512 + n]);
    float i_ = 1.f / (1.f + expf(-gi));
    float f_ = 1.f / (1.f + expf(-gf));
    float o_ = 1.f / (1.f + expf(-go));
    float cn = f_ * c + i_ * tanhf(gg);
    float hn = o_ * tanhf(cn);
    g_hall[((size_t)b * TMX + t) * 512 + n] = hn;
    if (t < (lens[b] - 1)) {
        g_hc[b * 1024 + n] = hn;
        g_hc[b * 1024 + 512 + n] = cn;
    }
}

// ---------------- persistent recurrence kernel (296 blocks x 256 thr) ----------------
__global__ void __launch_bounds__(256, 2) recur_kernel(
    const float* input, const int* lens,
    const float* dec_att_w, const float* dec_att_b,
    const float* att_w, const float* att_b,
    const float* actv_w, const float* actv_b,
    const float* wih, const float* whh,
    const float* bih, const float* bhh,
    float* outProbs)
{
    __shared__ char smem[SM_TOTAL];
    __shared__ int s_tk;
    const int blk = blockIdx.x;
    const int tid = threadIdx.x;

    for (int t = 0; t < TMX; t++) {
        // phase 1: hp = h @ [dec_att_w | actv_w]  (320 slabs: 20 cols x 16 splits, Kslab 32)
        {
            int r = blk;   // static first slab (blk < 296 < 320)
            for (;;) {
                gemm_body<HUGE_, 1024, 0, 1, 1, HUGE_, 512, 512, 2048, 2560, 32, 0, 0>(
                    g_hc, g_hc, g_hc, nullptr, dec_att_w, actv_w, 64,
                    g_hp, (long long)B_ * 2560, nullptr, nullptr,
                    r % 20, 0, r / 20, smem);
                if (tid == 0) s_tk = atomicAdd(&g_tk[t * 4 + 0], 1);
                __syncthreads();
                r = s_tk;
                __syncthreads();
                if (r >= HP_SLABS) break;
            }
        }
        gbar();

        // phase 2: attention (64 slabs, blocks < 148 only -> max 1/SM)
        if (blk < 64)
            attn_body(blk, t, input, dec_att_b, att_w, att_b, actv_b, lens, outProbs, smem);
        gbar();

        // phase 3: gates = [emb_t | gattv | h] @ [wih; whh]  (512 slabs: 16 cols x 32 splits, Kslab 96)
        {
            int r = blk;   // static first slab (blk < 296 < 512)
            for (;;) {
                gemm_body<512, 512, 2048, 2048, 1024, 2560, HUGE_, 2048, 2048, 2048, 96, 1, 0>(
                    g_emb + (size_t)t * B_ * 512, g_gattv, g_hc, nullptr, wih, whh, 64,
                    g_gs, (long long)B_ * 2048, nullptr, nullptr,
                    r & 15, 0, r >> 4, smem);
                if (tid == 0) s_tk = atomicAdd(&g_tk[t * 4 + 2], 1);
                __syncthreads();
                r = s_tk;
                __syncthreads();
                if (r >= GS_SLABS) break;
            }
        }
        gbar();

        // phase 4: lstm (128 slabs, blocks < 148 only -> max 1/SM)
        if (blk < 128) lstm_body(blk, t, bih, bhh, lens);
        gbar();
    }
}

// ---------------- small kernels ----------------
__global__ void mean_kernel(const float* __restrict__ in) {
    int idx = blockIdx.x * 256 + threadIdx.x;
    if (idx >= B_ * ENC_) return;
    int b = idx >> 11, e = idx & 2047;
    float s = 0.f;
#pragma unroll 7
    for (int l = 0; l < L_; l++) s += in[((size_t)b * L_ + l) * ENC_ + e];
    g_mean[idx] = s * (1.0f / 49.0f);
}

__global__ void hc_reduce(const float* __restrict__ hb, const float* __restrict__ cb) {
    int idx = blockIdx.x * 256 + threadIdx.x;
    int n = idx & 1023;
    float s = (n < 512) ? hb[n] : cb[n - 512];
#pragma unroll
    for (int zz = 0; zz < 16; zz++) s += g_hcslab[zz * (B_ * 1024) + idx];
    g_hc[idx] = s;
}

__global__ void enc_reduce(const float* __restrict__ eb) {
    int idx = blockIdx.x * 256 + threadIdx.x;
    g_encproj[idx] = g_encslab[idx] + g_encslab[3136 * 512 + idx] + eb[idx & 511];
}

__global__ void emb_gather(const float* __restrict__ embed_w, const int* __restrict__ captions) {
    int idx = blockIdx.x * 256 + threadIdx.x;
    if (idx >= TMX * B_ * 512) return;
    int e = idx & 511;
    int tb = idx >> 9;
    int b = tb & 63, t = tb >> 6;
    int tok = captions[b * 60 + t];
    g_emb[idx] = embed_w[(size_t)tok * 512 + e];
}

__global__ void rowmap_kernel(const int* __restrict__ lens) {
    __shared__ int off[B_ + 1];
    int tid = threadIdx.x;    // 64 threads
    if (tid == 0) {
        int acc = 0;
        for (int b = 0; b < B_; b++) {
            off[b] = acc;
            int pl = lens[b] - 1;
            if (pl < 0) pl = 0; if (pl > TMX) pl = TMX;
            acc += pl;
        }
        off[B_] = acc;
        g_nactive = acc;
    }
    __syncthreads();
    int pl = lens[tid] - 1;
    if (pl < 0) pl = 0; if (pl > TMX) pl = TMX;
    int o = off[tid];
    for (int t = 0; t < pl; t++) g_rowmap[o + t] = tid * TMX + t;
}

__global__ void tk_reset() {
    int i = threadIdx.x;     // 256 threads cover TMX*4 = 236
    if (i < TMX * 4) {
        int p = i & 3;
        g_tk[i] = (p == 0 || p == 2) ? NBLK : 0;   // static slabs = blockIdx, tickets start at NBLK
    }
}

__global__ void zerofill_kernel(const int* __restrict__ lens, float* __restrict__ out) {
    int row = blockIdx.x;     // 0..3775
    int b = row / TMX, t = row - b * TMX;
    if (t < lens[b] - 1) return;   // active row: fc writes it
    float4 z4 = make_float4(0.f, 0.f, 0.f, 0.f);
    float* o = out + (size_t)row * V_;
    for (int i = threadIdx.x * 4; i < V_; i += 512 * 4)
        *(float4*)&o[i] = z4;
}

// =====================================================================
extern "C" void kernel_launch(void* const* d_in, const int* in_sizes, int n_in,
                              void* d_out, int out_size)
{
    const float* input     = (const float*)d_in[0];
    const int*   captions  = (const int*)  d_in[1];
    const int*   lens      = (const int*)  d_in[2];
    const float* embed_w   = (const float*)d_in[3];
    const float* enc_att_w = (const float*)d_in[4];
    const float* enc_att_b = (const float*)d_in[5];
    const float* dec_att_w = (const float*)d_in[6];
    const float* dec_att_b = (const float*)d_in[7];
    const float* att_w     = (const float*)d_in[8];
    const float* att_b     = (const float*)d_in[9];
    const float* h_w       = (const float*)d_in[10];
    const float* h_b       = (const float*)d_in[11];
    const float* c_w       = (const float*)d_in[12];
    const float* c_b       = (const float*)d_in[13];
    const float* actv_w    = (const float*)d_in[14];
    const float* actv_b    = (const float*)d_in[15];
    const float* wih       = (const float*)d_in[16];
    const float* whh       = (const float*)d_in[17];
    const float* bih       = (const float*)d_in[18];
    const float* bhh       = (const float*)d_in[19];
    const float* fc_w      = (const float*)d_in[20];
    const float* fc_b      = (const float*)d_in[21];

    float* out      = (float*)d_out;
    float* outProbs = out + (size_t)B_ * TMX * V_;

    // 1) prep
    mean_kernel<<<(B_ * ENC_ + 255) / 256, 256>>>(input);
    gemm_h0c0<<<dim3(8, 1, 16), 256>>>(h_w, c_w);
    hc_reduce<<<(B_ * 1024) / 256, 256>>>(h_b, c_b);
    gemm_enc<<<dim3(4, 49, 2), 256>>>(input, enc_att_w);
    enc_reduce<<<(3136 * 512) / 256, 256>>>(enc_att_b);
    emb_gather<<<(TMX * B_ * 512 + 255) / 256, 256>>>(embed_w, captions);
    rowmap_kernel<<<1, 64>>>(lens);
    tk_reset<<<1, 256>>>();

    // 2) persistent recurrence (all 59 steps; ticket-balanced phases)
    recur_kernel<<<NBLK, 256>>>(input, lens, dec_att_w, dec_att_b,
                                att_w, att_b, actv_w, actv_b,
                                wih, whh, bih, bhh, outProbs);

    // 3) deferred fc over packed active rows + zero-fill of inactive rows
    zerofill_kernel<<<B_ * TMX, 512>>>(lens, out);
    gemm_fc<<<dim3(79, 59, 1), 256>>>(fc_w, fc_b, out);
}

// round 16
// speedup vs baseline: 1.1588x; 1.1588x over previous
#include <cuda_runtime.h>
#include <math.h>
#include <stdint.h>

typedef unsigned long long ull;

#define B_   64
#define L_   49
#define ENC_ 2048
#define TMX  59
#define V_   10000
#define BK   16
#define BM   64
#define BN   128
#define NBLK 256
#define HUGE_ 0x3FFFFFFF

#define ASTRIDE 68
#define SM_A_BYTES (2 * 16 * ASTRIDE * 4)          // 8704
#define SM_TOTAL   (SM_A_BYTES + 2 * 16 * 128 * 4) // 25088

// ---------------- scratch ----------------
__device__ float g_mean[B_ * ENC_];
__device__ float g_hc[B_ * 1024];
__device__ float g_hcslab[16 * B_ * 1024];
__device__ float g_encslab[2 * 3136 * 512];
__device__ float g_encproj[3136 * 512];
__device__ float g_emb[TMX * B_ * 512];
__device__ float g_hp[4 * B_ * 2560];
__device__ float g_gattv[B_ * 2048];
__device__ float g_gs[24 * B_ * 2048];       // slabs 0..7: G1 (emb+h), 8..23: G2 (gattv)
__device__ float g_hall[B_ * TMX * 512];     // row (b*59+t) x 512
__device__ int   g_rowmap[B_ * TMX];
__device__ int   g_nactive;
__device__ unsigned int g_bar_count;
__device__ unsigned int g_bar_gen;

// ---------------- f32x2 helpers ----------------
__device__ __forceinline__ ull pk2(float lo, float hi) {
    ull r; asm("mov.b64 %0, {%1,%2};" : "=l"(r) : "f"(lo), "f"(hi)); return r;
}
__device__ __forceinline__ void fma2(ull& d, ull a, ull b) {
    asm("fma.rn.f32x2 %0, %1, %2, %0;" : "+l"(d) : "l"(a), "l"(b));
}
__device__ __forceinline__ float2 upk2(ull v) {
    float2 f; asm("mov.b64 {%0,%1}, %2;" : "=f"(f.x), "=f"(f.y) : "l"(v)); return f;
}

// =====================================================================
// GEMM body (R8 state): 256 threads, BM=64, BN=128, BK=16, f32x2,
// 2-chunk-ahead global register pipeline over double-buffered smem.
// =====================================================================
template<int KA0, int LDA0, int KA1, int LDA1, int LDA2,
         int WSPLITK, int WSPLITN, int LDWA, int LDWB,
         int NTOT, int KSLAB, int GATHER, int EPI>
__device__ __forceinline__ void gemm_body(
    const float* __restrict__ A0, const float* __restrict__ A1,
    const float* __restrict__ A2, const int* __restrict__ rowIdx,
    const float* __restrict__ Wa, const float* __restrict__ Wb,
    int Mtot,
    float* __restrict__ Cslab, long long slabStride,
    const float* __restrict__ bias, float* __restrict__ outPred,
    int bx, int by, int z, char* smemRaw)
{
    float* As = (float*)smemRaw;                    // [2][16][ASTRIDE]
    float* Ws = (float*)(smemRaw + SM_A_BYTES);     // [2][16][128]

    const int tid  = threadIdx.x;
    const int w    = tid >> 5, lane = tid & 31;
    const int lr   = lane >> 2, lc = lane & 3;
    const int row0 = by * BM;
    const int kbase = z * KSLAB;
    const int mlim = (EPI == 2) ? g_nactive : Mtot;

    if (EPI == 2) {
        if (row0 >= mlim) return;
    }

    float4 avf0, avf1;
    float4 wvf0[2], wvf1[2];

    auto loadAv = [&](int kb) -> float4 {
        int m  = tid >> 2;
        int k4 = (tid & 3) * 4;
        int k  = kb + k4;
        int mg = row0 + m;
        float4 v = make_float4(0.f, 0.f, 0.f, 0.f);
        if (mg < mlim) {
            int arow = rowIdx ? rowIdx[mg] : mg;
            const float* Ap; int kr, lda;
            if (k < KA0)            { Ap = A0; kr = k;             lda = LDA0; }
            else if (k < KA0 + KA1) { Ap = A1; kr = k - KA0;       lda = LDA1; }
            else                    { Ap = A2; kr = k - KA0 - KA1; lda = LDA2; }
            v = __ldcg((const float4*)&Ap[(size_t)arow * lda + kr]);
        }
        return v;
    };
    auto loadWv = [&](int kb, float4* wv) {
#pragma unroll
        for (int p = 0; p < 2; p++) {
            int id = tid + p * 256;
            int k  = kb + (id >> 5);
            int j4 = (id & 31) * 4;
            int pc = GATHER ? ((j4 >> 5) * 512 + bx * 32 + (j4 & 31)) : (bx * BN + j4);
            const float* Wp = Wa; int kr = k, cc = pc, ldw = LDWA;
            if (k >= WSPLITK)       { Wp = Wb; kr = k - WSPLITK;  ldw = LDWB; }
            else if (pc >= WSPLITN) { Wp = Wb; cc = pc - WSPLITN; ldw = LDWB; }
            float4 v;
            if (pc + 3 < NTOT) {
                v = *(const float4*)&Wp[(size_t)kr * ldw + cc];
            } else {
                v.x = (pc     < NTOT) ? Wp[(size_t)kr * ldw + cc]     : 0.f;
                v.y = (pc + 1 < NTOT) ? Wp[(size_t)kr * ldw + cc + 1] : 0.f;
                v.z = (pc + 2 < NTOT) ? Wp[(size_t)kr * ldw + cc + 2] : 0.f;
                v.w = 0.f;
            }
            wv[p] = v;
        }
    };

    ull acc[4][4];
#pragma unroll
    for (int r = 0; r < 4; r++)
#pragma unroll
        for (int c = 0; c < 4; c++) acc[r][c] = 0ull;

    constexpr int nCh = KSLAB / BK;
    static_assert(nCh % 2 == 0, "nCh must be even");

#define STAGE_FRAG(BUF, AV, WV)                                        \
    do {                                                               \
        int m_ = tid >> 2, k4_ = (tid & 3) * 4;                        \
        float* a_ = As + ((BUF) * 16 + k4_) * ASTRIDE + m_;            \
        a_[0]           = (AV).x;                                      \
        a_[ASTRIDE]     = (AV).y;                                      \
        a_[2 * ASTRIDE] = (AV).z;                                      \
        a_[3 * ASTRIDE] = (AV).w;                                      \
        {                                                              \
            int k_ = tid >> 5, j4_ = (tid & 31) * 4;                   \
            *(float4*)&Ws[((BUF) * 16 + k_) * 128 + j4_] = (WV)[0];    \
        }                                                              \
        {                                                              \
            int id_ = tid + 256;                                       \
            int k_ = id_ >> 5, j4_ = (id_ & 31) * 4;                   \
            *(float4*)&Ws[((BUF) * 16 + k_) * 128 + j4_] = (WV)[1];    \
        }                                                              \
    } while (0)

#define COMPUTE_CHUNK(BUF)                                             \
    do {                                                               \
        const float* Ab = As + (BUF) * (16 * ASTRIDE) + lr * 8;        \
        const float* Wp = Ws + (BUF) * (16 * 128) + w * 16 + lc * 4;   \
        _Pragma("unroll")                                              \
        for (int kk = 0; kk < BK; kk++) {                              \
            float4 a0 = *(const float4*)(Ab + kk * ASTRIDE);           \
            float4 a1 = *(const float4*)(Ab + kk * ASTRIDE + 4);       \
            float4 w4 = *(const float4*)(Wp + kk * 128);               \
            ull p0 = *(ull*)&a0.x, p1 = *(ull*)&a0.z;                  \
            ull p2 = *(ull*)&a1.x, p3 = *(ull*)&a1.z;                  \
            ull d0 = pk2(w4.x, w4.x), d1 = pk2(w4.y, w4.y);            \
            ull d2 = pk2(w4.z, w4.z), d3 = pk2(w4.w, w4.w);            \
            fma2(acc[0][0], p0, d0); fma2(acc[0][1], p0, d1);          \
            fma2(acc[0][2], p0, d2); fma2(acc[0][3], p0, d3);          \
            fma2(acc[1][0], p1, d0); fma2(acc[1][1], p1, d1);          \
            fma2(acc[1][2], p1, d2); fma2(acc[1][3], p1, d3);          \
            fma2(acc[2][0], p2, d0); fma2(acc[2][1], p2, d1);          \
            fma2(acc[2][2], p2, d2); fma2(acc[2][3], p2, d3);          \
            fma2(acc[3][0], p3, d0); fma2(acc[3][1], p3, d1);          \
            fma2(acc[3][2], p3, d2); fma2(acc[3][3], p3, d3);          \
        }                                                              \
    } while (0)

    avf0 = loadAv(kbase);            loadWv(kbase, wvf0);
    if (nCh > 1) { avf1 = loadAv(kbase + BK); loadWv(kbase + BK, wvf1); }
    STAGE_FRAG(0, avf0, wvf0);
    __syncthreads();

#pragma unroll 1
    for (int ch = 0; ch < nCh; ch += 2) {
        if (ch + 2 < nCh) { avf0 = loadAv(kbase + (ch + 2) * BK); loadWv(kbase + (ch + 2) * BK, wvf0); }
        COMPUTE_CHUNK(0);
        if (ch + 1 < nCh) STAGE_FRAG(1, avf1, wvf1);
        __syncthreads();

        if (ch + 3 < nCh) { avf1 = loadAv(kbase + (ch + 3) * BK); loadWv(kbase + (ch + 3) * BK, wvf1); }
        COMPUTE_CHUNK(1);
        if (ch + 2 < nCh) STAGE_FRAG(0, avf0, wvf0);
        __syncthreads();
    }
#undef STAGE_FRAG
#undef COMPUTE_CHUNK

    const int j0 = w * 16 + lc * 4;
#pragma unroll
    for (int rp = 0; rp < 4; rp++) {
#pragma unroll
        for (int half = 0; half < 2; half++) {
            int ml = row0 + lr * 8 + rp * 2 + half;
            if (ml >= mlim) continue;
            float v[4];
#pragma unroll
            for (int c = 0; c < 4; c++) {
                float2 f = upk2(acc[rp][c]);
                v[c] = half ? f.y : f.x;
            }
            if (EPI == 2) {
                int orow = rowIdx[ml];
                size_t base = (size_t)orow * V_;
                int pc0 = bx * BN + j0;
                if (pc0 + 3 < NTOT) {
                    float4 o;
                    o.x = v[0] + bias[pc0];     o.y = v[1] + bias[pc0 + 1];
                    o.z = v[2] + bias[pc0 + 2]; o.w = v[3] + bias[pc0 + 3];
                    *(float4*)&outPred[base + pc0] = o;
                } else {
#pragma unroll
                    for (int c = 0; c < 4; c++) {
                        int pc = pc0 + c;
                        if (pc < NTOT) outPred[base + pc] = v[c] + bias[pc];
                    }
                }
            } else {
                int pc0 = GATHER ? ((j0 >> 5) * 512 + bx * 32 + (j0 & 31)) : (bx * BN + j0);
                float* o = Cslab + (size_t)z * slabStride + (size_t)ml * NTOT + pc0;
                *(float4*)&o[0] = make_float4(v[0], v[1], v[2], v[3]);
            }
        }
    }
}

// ---------------- standalone GEMM wrappers ----------------
__global__ void __launch_bounds__(256, 2) gemm_h0c0(
    const float* h_w, const float* c_w)
{
    __shared__ char smem[SM_TOTAL];
    gemm_body<HUGE_, 2048, 0, 1, 1, HUGE_, 512, 512, 512, 1024, 128, 0, 0>(
        g_mean, g_mean, g_mean, nullptr, h_w, c_w, 64,
        g_hcslab, (long long)B_ * 1024, nullptr, nullptr,
        blockIdx.x, 0, blockIdx.z, smem);
}

__global__ void __launch_bounds__(256, 2) gemm_enc(
    const float* input, const float* enc_att_w)
{
    __shared__ char smem[SM_TOTAL];
    gemm_body<HUGE_, 2048, 0, 1, 1, HUGE_, HUGE_, 512, 512, 512, 1024, 0, 0>(
        input, input, input, nullptr, enc_att_w, enc_att_w, 3136,
        g_encslab, (long long)3136 * 512, nullptr, nullptr,
        blockIdx.x, blockIdx.y, blockIdx.z, smem);
}

__global__ void __launch_bounds__(256, 2) gemm_fc(
    const float* fc_w, const float* fc_b, float* out)
{
    __shared__ char smem[SM_TOTAL];
    gemm_body<HUGE_, 512, 0, 1, 1, HUGE_, HUGE_, V_, V_, V_, 512, 0, 2>(
        g_hall, g_hall, g_hall, g_rowmap, fc_w, fc_w, B_ * TMX,
        nullptr, 0, fc_b, out,
        blockIdx.x, blockIdx.y, 0, smem);
}

// ---------------- flat grid barrier (256 arrivals, R8 form) ----------------
__device__ __forceinline__ void gbar() {
    __syncthreads();
    if (threadIdx.x == 0) {
        __threadfence();
        unsigned int gen = *(volatile unsigned int*)&g_bar_gen;
        unsigned int arrived = atomicAdd(&g_bar_count, 1u);
        if (arrived == NBLK - 1) {
            g_bar_count = 0;
            __threadfence();
            atomicAdd(&g_bar_gen, 1u);
        } else {
            while (*(volatile unsigned int*)&g_bar_gen == gen) {}
        }
        __threadfence();
    }
    __syncthreads();
}

// ---------------- attention phase (one block per b, 256 threads) ----------------
__device__ void attn_body(int b, int t,
    const float* __restrict__ input,
    const float* __restrict__ dec_b,
    const float* __restrict__ att_w,
    const float* __restrict__ att_b,
    const float* __restrict__ actv_b,
    const int* __restrict__ lens,
    float* __restrict__ outProbs, char* smemRaw)
{
    float* sd = (float*)smemRaw;   // 512
    float* sp = sd + 512;          // 64
    const int tid = threadIdx.x;

    for (int i = tid; i < 512; i += 256) {
        float s = dec_b[i];
#pragma unroll
        for (int zz = 0; zz < 4; zz++) s += __ldcg(&g_hp[zz * (B_ * 2560) + b * 2560 + i]);
        sd[i] = s;
    }
    __syncthreads();

    const int w = tid >> 5, lane = tid & 31;
    for (int l = w; l < L_; l += 8) {
        const float* ep = g_encproj + ((size_t)b * L_ + l) * 512;
        float s = 0.f;
#pragma unroll
        for (int a = lane; a < 512; a += 32) {
            float v = fmaxf(ep[a] + sd[a], 0.f);
            s = fmaf(v, att_w[a], s);
        }
#pragma unroll
        for (int o = 16; o; o >>= 1) s += __shfl_xor_sync(~0u, s, o);
        if (lane == 0) sp[l] = s + att_b[0];
    }
    __syncthreads();

    if (w == 0) {
        float v0 = (lane < L_) ? sp[lane] : -1e30f;
        float v1 = (lane + 32 < L_) ? sp[lane + 32] : -1e30f;
        float mx = fmaxf(v0, v1);
#pragma unroll
        for (int o = 16; o; o >>= 1) mx = fmaxf(mx, __shfl_xor_sync(~0u, mx, o));
        float e0 = (lane < L_) ? expf(v0 - mx) : 0.f;
        float e1 = (lane + 32 < L_) ? expf(v1 - mx) : 0.f;
        float sm = e0 + e1;
#pragma unroll
        for (int o = 16; o; o >>= 1) sm += __shfl_xor_sync(~0u, sm, o);
        float inv = 1.f / sm;
        if (lane < L_) sp[lane] = e0 * inv;
        if (lane + 32 < L_) sp[lane + 32] = e1 * inv;
    }
    __syncthreads();

    const bool act = t < (lens[b] - 1);
    if (tid < L_) outProbs[((size_t)b * TMX + t) * L_ + tid] = act ? sp[tid] : 0.f;

    const int e0i = tid * 8;
    float4 a0 = make_float4(0, 0, 0, 0), a1 = make_float4(0, 0, 0, 0);
    const float* ip = input + (size_t)b * L_ * ENC_ + e0i;
    for (int l = 0; l < L_; l++) {
        float p = sp[l];
        float4 x0 = *(const float4*)(ip + (size_t)l * ENC_);
        float4 x1 = *(const float4*)(ip + (size_t)l * ENC_ + 4);
        a0.x = fmaf(p, x0.x, a0.x); a0.y = fmaf(p, x0.y, a0.y);
        a0.z = fmaf(p, x0.z, a0.z); a0.w = fmaf(p, x0.w, a0.w);
        a1.x = fmaf(p, x1.x, a1.x); a1.y = fmaf(p, x1.y, a1.y);
        a1.z = fmaf(p, x1.z, a1.z); a1.w = fmaf(p, x1.w, a1.w);
    }
    float res[8] = {a0.x, a0.y, a0.z, a0.w, a1.x, a1.y, a1.z, a1.w};
#pragma unroll
    for (int i = 0; i < 8; i++) {
        int e = e0i + i;
        float hp = actv_b[e];
#pragma unroll
        for (int zz = 0; zz < 4; zz++) hp += __ldcg(&g_hp[zz * (B_ * 2560) + b * 2560 + 512 + e]);
        float gate = 1.f / (1.f + expf(-hp));
        g_gattv[b * ENC_ + e] = gate * res[i];
    }
}

// ---------------- lstm phase (128 blocks x 256 threads, 24 slabs) ----------------
__device__ void lstm_body(int blk, int t,
    const float* __restrict__ bih, const float* __restrict__ bhh,
    const int* __restrict__ lens)
{
    int idx = blk * 256 + threadIdx.x;        // 64*512
    int b = idx >> 9, n = idx & 511;
    float gi = bih[n]        + bhh[n];
    float gf = bih[n + 512]  + bhh[n + 512];
    float gg = bih[n + 1024] + bhh[n + 1024];
    float go = bih[n + 1536] + bhh[n + 1536];
#pragma unroll
    for (int zz = 0; zz < 24; zz++) {
        const float* gs = g_gs + zz * (B_ * 2048) + b * 2048;
        gi += __ldcg(&gs[n]);        gf += __ldcg(&gs[n + 512]);
        gg += __ldcg(&gs[n + 1024]); go += __ldcg(&gs[n + 1536]);
    }
    float c  = __ldcg(&g_hc[b * 1024 + 512 + n]);
    float i_ = 1.f / (1.f + expf(-gi));
    float f_ = 1.f / (1.f + expf(-gf));
    float o_ = 1.f / (1.f + expf(-go));
    float cn = f_ * c + i_ * tanhf(gg);
    float hn = o_ * tanhf(cn);
    g_hall[((size_t)b * TMX + t) * 512 + n] = hn;
    if (t < (lens[b] - 1)) {
        g_hc[b * 1024 + n] = hn;
        g_hc[b * 1024 + 512 + n] = cn;
    }
}

// ---------------- persistent recurrence kernel (256 blocks x 256 thr) ----------------
__global__ void __launch_bounds__(256, 2) recur_kernel(
    const float* input, const int* lens,
    const float* dec_att_w, const float* dec_att_b,
    const float* att_w, const float* att_b,
    const float* actv_w, const float* actv_b,
    const float* wih, const float* whh,
    const float* bih, const float* bhh,
    float* outProbs)
{
    __shared__ char smem[SM_TOTAL];
    const int blk = blockIdx.x;

    for (int t = 0; t < TMX; t++) {
        // phase 1 (parallel):
        //   blocks 0..79:    hp = h @ [dec_att_w | actv_w]  (20 cols x 4 splits, Kslab 128)
        //   blocks 80..207:  G1 = [emb_t | h] @ [wih[0:512]; whh]  (16 cols x 8 splits, Kslab 128)
        if (blk < 80) {
            gemm_body<HUGE_, 1024, 0, 1, 1, HUGE_, 512, 512, 2048, 2560, 128, 0, 0>(
                g_hc, g_hc, g_hc, nullptr, dec_att_w, actv_w, 64,
                g_hp, (long long)B_ * 2560, nullptr, nullptr,
                blk % 20, 0, blk / 20, smem);
        } else if (blk < 208) {
            int r = blk - 80;
            gemm_body<512, 512, 512, 1024, 1, 512, HUGE_, 2048, 2048, 2048, 128, 1, 0>(
                g_emb + (size_t)t * B_ * 512, g_hc, g_hc, nullptr, wih, whh, 64,
                g_gs, (long long)B_ * 2048, nullptr, nullptr,
                r & 15, 0, r >> 4, smem);
        }
        gbar();

        // phase 2: attention + softmax + att_vec + gate
        if (blk < 64)
            attn_body(blk, t, input, dec_att_b, att_w, att_b, actv_b, lens, outProbs, smem);
        gbar();

        // phase 3: G2 = gattv @ wih[512:2560]  (16 cols x 16 splits, Kslab 128)
        gemm_body<HUGE_, 2048, 0, 1, 1, HUGE_, HUGE_, 2048, 2048, 2048, 128, 1, 0>(
            g_gattv, g_gattv, g_gattv, nullptr, wih + (size_t)512 * 2048, wih + (size_t)512 * 2048, 64,
            g_gs + (size_t)8 * B_ * 2048, (long long)B_ * 2048, nullptr, nullptr,
            blk & 15, 0, blk >> 4, smem);
        gbar();

        // phase 4: slab reduce (24) + LSTM pointwise + carry update
        if (blk < 128) lstm_body(blk, t, bih, bhh, lens);
        gbar();
    }
}

// ---------------- small kernels ----------------
__global__ void mean_kernel(const float* __restrict__ in) {
    int idx = blockIdx.x * 256 + threadIdx.x;
    if (idx >= B_ * ENC_) return;
    int b = idx >> 11, e = idx & 2047;
    float s = 0.f;
#pragma unroll 7
    for (int l = 0; l < L_; l++) s += in[((size_t)b * L_ + l) * ENC_ + e];
    g_mean[idx] = s * (1.0f / 49.0f);
}

__global__ void hc_reduce(const float* __restrict__ hb, const float* __restrict__ cb) {
    int idx = blockIdx.x * 256 + threadIdx.x;
    int n = idx & 1023;
    float s = (n < 512) ? hb[n] : cb[n - 512];
#pragma unroll
    for (int zz = 0; zz < 16; zz++) s += g_hcslab[zz * (B_ * 1024) + idx];
    g_hc[idx] = s;
}

__global__ void enc_reduce(const float* __restrict__ eb) {
    int idx = blockIdx.x * 256 + threadIdx.x;
    g_encproj[idx] = g_encslab[idx] + g_encslab[3136 * 512 + idx] + eb[idx & 511];
}

__global__ void emb_gather(const float* __restrict__ embed_w, const int* __restrict__ captions) {
    int idx = blockIdx.x * 256 + threadIdx.x;
    if (idx >= TMX * B_ * 512) return;
    int e = idx & 511;
    int tb = idx >> 9;
    int b = tb & 63, t = tb >> 6;
    int tok = captions[b * 60 + t];
    g_emb[idx] = embed_w[(size_t)tok * 512 + e];
}

__global__ void rowmap_kernel(const int* __restrict__ lens) {
    __shared__ int off[B_ + 1];
    int tid = threadIdx.x;    // 64 threads
    if (tid == 0) {
        int acc = 0;
        for (int b = 0; b < B_; b++) {
            off[b] = acc;
            int pl = lens[b] - 1;
            if (pl < 0) pl = 0; if (pl > TMX) pl = TMX;
            acc += pl;
        }
        off[B_] = acc;
        g_nactive = acc;
    }
    __syncthreads();
    int pl = lens[tid] - 1;
    if (pl < 0) pl = 0; if (pl > TMX) pl = TMX;
    int o = off[tid];
    for (int t = 0; t < pl; t++) g_rowmap[o + t] = tid * TMX + t;
}

__global__ void zerofill_kernel(const int* __restrict__ lens, float* __restrict__ out) {
    int row = blockIdx.x;     // 0..3775
    int b = row / TMX, t = row - b * TMX;
    if (t < lens[b] - 1) return;   // active row: fc writes it
    float4 z4 = make_float4(0.f, 0.f, 0.f, 0.f);
    float* o = out + (size_t)row * V_;
    for (int i = threadIdx.x * 4; i < V_; i += 512 * 4)
        *(float4*)&o[i] = z4;
}

// =====================================================================
extern "C" void kernel_launch(void* const* d_in, const int* in_sizes, int n_in,
                              void* d_out, int out_size)
{
    const float* input     = (const float*)d_in[0];
    const int*   captions  = (const int*)  d_in[1];
    const int*   lens      = (const int*)  d_in[2];
    const float* embed_w   = (const float*)d_in[3];
    const float* enc_att_w = (const float*)d_in[4];
    const float* enc_att_b = (const float*)d_in[5];
    const float* dec_att_w = (const float*)d_in[6];
    const float* dec_att_b = (const float*)d_in[7];
    const float* att_w     = (const float*)d_in[8];
    const float* att_b     = (const float*)d_in[9];
    const float* h_w       = (const float*)d_in[10];
    const float* h_b       = (const float*)d_in[11];
    const float* c_w       = (const float*)d_in[12];
    const float* c_b       = (const float*)d_in[13];
    const float* actv_w    = (const float*)d_in[14];
    const float* actv_b    = (const float*)d_in[15];
    const float* wih       = (const float*)d_in[16];
    const float* whh       = (const float*)d_in[17];
    const float* bih       = (const float*)d_in[18];
    const float* bhh       = (const float*)d_in[19];
    const float* fc_w      = (const float*)d_in[20];
    const float* fc_b      = (const float*)d_in[21];

    float* out      = (float*)d_out;
    float* outProbs = out + (size_t)B_ * TMX * V_;

    // 1) prep
    mean_kernel<<<(B_ * ENC_ + 255) / 256, 256>>>(input);
    gemm_h0c0<<<dim3(8, 1, 16), 256>>>(h_w, c_w);
    hc_reduce<<<(B_ * 1024) / 256, 256>>>(h_b, c_b);
    gemm_enc<<<dim3(4, 49, 2), 256>>>(input, enc_att_w);
    enc_reduce<<<(3136 * 512) / 256, 256>>>(enc_att_b);
    emb_gather<<<(TMX * B_ * 512 + 255) / 256, 256>>>(embed_w, captions);
    rowmap_kernel<<<1, 64>>>(lens);

    // 2) persistent recurrence (all 59 steps; hp || G1, attn, G2, lstm)
    recur_kernel<<<NBLK, 256>>>(input, lens, dec_att_w, dec_att_b,
                                att_w, att_b, actv_w, actv_b,
                                wih, whh, bih, bhh, outProbs);

    // 3) deferred fc over packed active rows + zero-fill of inactive rows
    zerofill_kernel<<<B_ * TMX, 512>>>(lens, out);
    gemm_fc<<<dim3(79, 59, 1), 256>>>(fc_w, fc_b, out);
}